// round 9
// baseline (speedup 1.0000x reference)
#include <cuda_runtime.h>
#include <cstdint>

// Problem constants
#define BB 2
#define DD 512
#define CC 512
#define TT 32
#define TDIM 1024
#define HH 8
#define FF 64
#define SCALE 0.125f   // F^-0.5

#define M_QKV (BB*DD*TT)       // 32768
#define N_QKV (3*CC)           // 1536

// ---------------- scratch ----------------
__device__ float g_xt  [BB*DD*TT*CC];        // normalized, transposed x  [B,D,T,C]
__device__ float g_qkv [BB*DD*TT*3*CC];      // [B,D,T,3C]
__device__ float g_tprj[3*BB*TT*CC];         // [p,B,T,C]
__device__ float g_R   [3*BB*TT*TT*CC];      // rpe bias  [p,B,T,S,C]
__device__ float g_ao  [BB*DD*TT*CC];        // attention output pre-proj [B,D,T,C]

// ---------------- GroupNorm + transpose ----------------
__global__ __launch_bounds__(512) void groupnorm_kernel(
    const float* __restrict__ x, const float* __restrict__ w,
    const float* __restrict__ bv, float* __restrict__ xt)
{
    int bd = blockIdx.x;
    int c  = threadIdx.x;
    const float* xr = x + (size_t)bd * CC * TT + (size_t)c * TT;
    float v[TT];
    float s = 0.f, ss = 0.f;
#pragma unroll
    for (int i = 0; i < TT/4; i++) {
        float4 t4 = *(const float4*)(xr + i*4);
        v[i*4+0]=t4.x; v[i*4+1]=t4.y; v[i*4+2]=t4.z; v[i*4+3]=t4.w;
        s += t4.x+t4.y+t4.z+t4.w;
        ss += t4.x*t4.x + t4.y*t4.y + t4.z*t4.z + t4.w*t4.w;
    }
#pragma unroll
    for (int off = 8; off >= 1; off >>= 1) {
        s  += __shfl_xor_sync(0xffffffffu, s,  off);
        ss += __shfl_xor_sync(0xffffffffu, ss, off);
    }
    float mean = s * (1.f/512.f);
    float var  = ss * (1.f/512.f) - mean*mean;
    float rstd = rsqrtf(var + 1e-5f);
    float gw = w[c] * rstd;
    float gb = bv[c] - mean * gw;
    float* dst = xt + (size_t)bd * TT * CC + c;
#pragma unroll
    for (int t = 0; t < TT; t++) dst[(size_t)t*CC] = fmaf(v[t], gw, gb);
}

// ---------------- tf32 tensor-core NT GEMM, cp.async double-buffered ----------------
// MODE 0: plain store. MODE 1: +resid, transposed store. MODE 2: A computed on the
// fly as silu(tproj + dist-feats) (fused RPE h), A param = tproj base.
#define GS 36
#define GSTAGE (128*GS)
#define GEMM_SMEM (4*GSTAGE*4)   // 2 stages x (A+B) = 73728 bytes

__device__ __forceinline__ void cp16(uint32_t dst, const float* src, int sz) {
    asm volatile("cp.async.cg.shared.global [%0], [%1], 16, %2;\n"
                 :: "r"(dst), "l"(src), "r"(sz));
}

template<int MODE>
__global__ __launch_bounds__(256, 2) void gemm_tf32(
    const float* __restrict__ A,
    const float* __restrict__ W0, const float* __restrict__ W1, const float* __restrict__ W2,
    const float* __restrict__ B0, const float* __restrict__ B1, const float* __restrict__ B2,
    float* __restrict__ out, const float* __restrict__ resid,
    const int* __restrict__ fi,
    const float* __restrict__ dw0, const float* __restrict__ dw1, const float* __restrict__ dw2,
    const float* __restrict__ db0, const float* __restrict__ db1, const float* __restrict__ db2,
    int M, int N, int K, int rows_per_w, size_t out_z_stride)
{
    extern __shared__ float sh[];
    float* As = sh;             // [2][128][GS]
    float* Bs = sh + 2*GSTAGE;  // [2][128][GS]

    int bm = blockIdx.y * 128, bn = blockIdx.x * 128;
    int p = (gridDim.z > 1) ? blockIdx.z : (bm / rows_per_w);
    const float* W    = (p == 0) ? W0 : ((p == 1) ? W1 : W2);
    const float* bias = (p == 0) ? B0 : ((p == 1) ? B1 : B2);
    float* outp = out + (size_t)blockIdx.z * out_z_stride;

    int tid  = threadIdx.x;
    int warp = tid >> 5, lane = tid & 31;
    int gq = lane >> 2, tg = lane & 3;
    int wm = (warp >> 1) * 32;
    int wn = (warp & 1) * 64;

    int lrow = tid >> 1;           // 0..127
    int lk   = (tid & 1) * 16;     // 0 or 16

    const float* Ap = A + (size_t)(bm + lrow) * K + lk;
    const float* Wp = W + (size_t)(bn + lrow) * K + lk;
    int a_sz = ((bm + lrow) < M) ? 16 : 0;
    uint32_t sA = (uint32_t)__cvta_generic_to_shared(As + lrow*GS + lk);
    uint32_t sB = (uint32_t)__cvta_generic_to_shared(Bs + lrow*GS + lk);

    // MODE 2 per-row precompute: row = (p,b,t,s) in [0,6144)
    float rf0 = 0.f, rf1 = 0.f, rf2 = 0.f;
    const float* dwp = nullptr; const float* dbp = nullptr;
    const float* trow = nullptr;
    if (MODE == 2) {
        int grow = bm + lrow;
        int pp = grow >> 11;
        int bb = (grow >> 10) & 1;
        int tt = (grow >> 5) & 31;
        int sr = grow & 31;
        dwp = (pp == 0) ? dw0 : ((pp == 1) ? dw1 : dw2);
        dbp = (pp == 0) ? db0 : ((pp == 1) ? db1 : db2);
        int dr = fi[bb*TT + tt] - fi[bb*TT + sr];
        float df = (float)dr;
        rf0 = log1pf(fmaxf(df, 0.f));
        rf1 = log1pf(fmaxf(-df, 0.f));
        rf2 = (dr == 0) ? 1.f : 0.f;
        trow = A + ((size_t)(pp*BB + bb)*TT + tt) * CC;
    }

    float acc[2][8][4] = {};
    int nt = K >> 5;

    // --- stage fill helpers (inlined twice) ---
    // prologue: stage 0
    if (MODE == 2) {
        float* dstA = As + lrow*GS + lk;
#pragma unroll
        for (int v = 0; v < 4; v++) {
#pragma unroll
            for (int j = 0; j < 4; j++) {
                int c = lk + v*4 + j;
                float e = trow[c] + dwp[c*3]*rf0 + dwp[c*3+1]*rf1 + dwp[c*3+2]*rf2 + dbp[c];
                float sg = 1.f / (1.f + __expf(-e));
                dstA[v*4+j] = e * sg;
            }
        }
    } else {
#pragma unroll
        for (int v = 0; v < 4; v++) cp16(sA + v*16, Ap + v*4, a_sz);
    }
#pragma unroll
    for (int v = 0; v < 4; v++) cp16(sB + v*16, Wp + v*4, 16);
    asm volatile("cp.async.commit_group;\n");

    for (int it = 0; it < nt; it++) {
        int cur = it & 1;
        if (it + 1 < nt) {
            int k0 = (it+1)*32;
            if (MODE == 2) {
                float* dstA = As + (cur^1)*GSTAGE + lrow*GS + lk;
#pragma unroll
                for (int v = 0; v < 4; v++) {
#pragma unroll
                    for (int j = 0; j < 4; j++) {
                        int c = k0 + lk + v*4 + j;
                        float e = trow[c] + dwp[c*3]*rf0 + dwp[c*3+1]*rf1 + dwp[c*3+2]*rf2 + dbp[c];
                        float sg = 1.f / (1.f + __expf(-e));
                        dstA[v*4+j] = e * sg;
                    }
                }
            } else {
                uint32_t da = sA + (cur^1)*(GSTAGE*4);
#pragma unroll
                for (int v = 0; v < 4; v++) cp16(da + v*16, Ap + k0 + v*4, a_sz);
            }
            uint32_t db = sB + (cur^1)*(GSTAGE*4);
#pragma unroll
            for (int v = 0; v < 4; v++) cp16(db + v*16, Wp + k0 + v*4, 16);
            asm volatile("cp.async.commit_group;\n");
            asm volatile("cp.async.wait_group 1;\n");
        } else {
            asm volatile("cp.async.wait_group 0;\n");
        }
        __syncthreads();

        const float* Ac = As + cur*GSTAGE;
        const float* Bc = Bs + cur*GSTAGE;
#pragma unroll
        for (int ks = 0; ks < 4; ks++) {
            int kk = ks * 8;
            unsigned a[2][4];
#pragma unroll
            for (int i = 0; i < 2; i++) {
                int m = wm + i*16 + gq;
                a[i][0] = __float_as_uint(Ac[(m    )*GS + kk + tg    ]);
                a[i][1] = __float_as_uint(Ac[(m + 8)*GS + kk + tg    ]);
                a[i][2] = __float_as_uint(Ac[(m    )*GS + kk + tg + 4]);
                a[i][3] = __float_as_uint(Ac[(m + 8)*GS + kk + tg + 4]);
            }
            unsigned bf[8][2];
#pragma unroll
            for (int j = 0; j < 8; j++) {
                int n = wn + j*8 + gq;
                bf[j][0] = __float_as_uint(Bc[n*GS + kk + tg    ]);
                bf[j][1] = __float_as_uint(Bc[n*GS + kk + tg + 4]);
            }
#pragma unroll
            for (int i = 0; i < 2; i++)
#pragma unroll
                for (int j = 0; j < 8; j++) {
                    asm volatile(
                        "mma.sync.aligned.m16n8k8.row.col.f32.tf32.tf32.f32 "
                        "{%0,%1,%2,%3}, {%4,%5,%6,%7}, {%8,%9}, {%0,%1,%2,%3};\n"
                        : "+f"(acc[i][j][0]), "+f"(acc[i][j][1]),
                          "+f"(acc[i][j][2]), "+f"(acc[i][j][3])
                        : "r"(a[i][0]), "r"(a[i][1]), "r"(a[i][2]), "r"(a[i][3]),
                          "r"(bf[j][0]), "r"(bf[j][1]));
                }
        }
        __syncthreads();
    }

    // epilogue
#pragma unroll
    for (int i = 0; i < 2; i++) {
        int m0 = bm + wm + i*16 + gq;
        int m1 = m0 + 8;
#pragma unroll
        for (int j = 0; j < 8; j++) {
            int n0 = bn + wn + j*8 + tg*2;
            float bn0 = bias[n0], bn1 = bias[n0+1];
            float v00 = acc[i][j][0] + bn0, v01 = acc[i][j][1] + bn1;
            float v10 = acc[i][j][2] + bn0, v11 = acc[i][j][3] + bn1;
            if (MODE == 1) {
                v00 += resid[(size_t)m0*N + n0];
                v01 += resid[(size_t)m0*N + n0+1];
                v10 += resid[(size_t)m1*N + n0];
                v11 += resid[(size_t)m1*N + n0+1];
                size_t b0 = (size_t)(m0 >> 5) * (512*32);
                size_t b1 = (size_t)(m1 >> 5) * (512*32);
                outp[b0 + (size_t)(n0  )*32 + (m0 & 31)] = v00;
                outp[b0 + (size_t)(n0+1)*32 + (m0 & 31)] = v01;
                outp[b1 + (size_t)(n0  )*32 + (m1 & 31)] = v10;
                outp[b1 + (size_t)(n0+1)*32 + (m1 & 31)] = v11;
            } else {
                if (m0 < M) { outp[(size_t)m0*N + n0] = v00; outp[(size_t)m0*N + n0+1] = v01; }
                if (m1 < M) { outp[(size_t)m1*N + n0] = v10; outp[(size_t)m1*N + n0+1] = v11; }
            }
        }
    }
}

// ---------------- attention: block per (b, d-group of 4, h), 4 blocks/SM ----------------
#define NG 4
#define KST 68
#define ATTN_SMEM ((NG*32*KST + NG*32*33)*4 + 128)

__global__ __launch_bounds__(256, 4) void attn_kernel(
    const float* __restrict__ qkv, const float* __restrict__ R,
    const int* __restrict__ mask, float* __restrict__ ao)
{
    extern __shared__ float sm[];
    float* kv = sm;                    // [NG*32][KST], K then V
    float* at = kv + NG*32*KST;        // [NG][32*33]
    int*  msk = (int*)(at + NG*32*33);

    int tid = threadIdx.x;
    int h = blockIdx.x & 7;
    int g = blockIdx.x >> 3;           // 0 .. B*(D/NG)-1 = 255
    int b = g >> 7;                    // D/NG = 128
    int d0 = (g & 127) * NG;
    int bd0 = b*DD + d0;

    // load K tiles for NG d's
    for (int e = tid; e < NG*32*16; e += 256) {
        int dd = e >> 9;
        int t  = (e >> 4) & 31;
        int f  = (e & 15) * 4;
        const float* rowp = qkv + ((size_t)(bd0+dd)*TT + t)*N_QKV + h*FF + f;
        *(float4*)&kv[(dd*32 + t)*KST + f] = *(const float4*)(rowp + 512);
    }
    if (tid < 32) msk[tid] = mask[b*TT + tid];
    __syncthreads();

    const float* Rqb = R + (size_t)(0*BB + b)*(TT*TT*CC) + h*FF;
    const float* Rkb = R + (size_t)(1*BB + b)*(TT*TT*CC) + h*FF;
    const float* Rvb = R + (size_t)(2*BB + b)*(TT*TT*CC) + h*FF;

    // scores: attn = SCALE * (q.k + q.Rk + k.Rq)
#pragma unroll 1
    for (int pi = 0; pi < 4; pi++) {
        int pid = pi*256 + tid;
        int t = pid >> 5, s = pid & 31;
        const float* rk = Rkb + (size_t)(t*TT + s)*CC;
        const float* rq = Rqb + (size_t)(s*TT + t)*CC;
        const float* qb = qkv + ((size_t)bd0*TT + t)*N_QKV + h*FF;
        float acc[NG] = {}, accq[NG] = {};
#pragma unroll
        for (int f = 0; f < FF; f += 4) {
            float4 rk4 = *(const float4*)(rk + f);
            float4 rq4 = *(const float4*)(rq + f);
#pragma unroll
            for (int dd = 0; dd < NG; dd++) {
                float4 q4 = *(const float4*)(qb + (size_t)dd*TT*N_QKV + f);
                float4 k4 = *(const float4*)&kv[(dd*32 + s)*KST + f];
                acc[dd]  = fmaf(q4.x, k4.x + rk4.x, acc[dd]);
                acc[dd]  = fmaf(q4.y, k4.y + rk4.y, acc[dd]);
                acc[dd]  = fmaf(q4.z, k4.z + rk4.z, acc[dd]);
                acc[dd]  = fmaf(q4.w, k4.w + rk4.w, acc[dd]);
                accq[dd] = fmaf(k4.x, rq4.x, accq[dd]);
                accq[dd] = fmaf(k4.y, rq4.y, accq[dd]);
                accq[dd] = fmaf(k4.z, rq4.z, accq[dd]);
                accq[dd] = fmaf(k4.w, rq4.w, accq[dd]);
            }
        }
        bool bad = (msk[t] != msk[s]);
#pragma unroll
        for (int dd = 0; dd < NG; dd++)
            at[dd*(32*33) + t*33 + s] = bad ? -1e30f : SCALE*(acc[dd] + accq[dd]);
    }
    __syncthreads();

    // softmax: NG*32 = 128 rows
    if (tid < NG*32) {
        int dd = tid >> 5, t = tid & 31;
        float* row = &at[dd*(32*33) + t*33];
        float mx = -1e30f;
#pragma unroll
        for (int s = 0; s < 32; s++) mx = fmaxf(mx, row[s]);
        float sum = 0.f;
#pragma unroll
        for (int s = 0; s < 32; s++) { float e = __expf(row[s] - mx); row[s] = e; sum += e; }
        float inv = 1.f / sum;
#pragma unroll
        for (int s = 0; s < 32; s++) row[s] *= inv;
    }
    __syncthreads();

    // load V into the same buffer
    for (int e = tid; e < NG*32*16; e += 256) {
        int dd = e >> 9;
        int t  = (e >> 4) & 31;
        int f  = (e & 15) * 4;
        const float* rowp = qkv + ((size_t)(bd0+dd)*TT + t)*N_QKV + h*FF + f;
        *(float4*)&kv[(dd*32 + t)*KST + f] = *(const float4*)(rowp + 1024);
    }
    __syncthreads();

    // out = attn @ (V + Rv)
#pragma unroll 1
    for (int ui = 0; ui < 2; ui++) {
        int u = ui*256 + tid;
        int t = u >> 4, f = (u & 15) * 4;
        const float* rv = Rvb + (size_t)(t*TT)*CC + f;
        float4 o[NG];
#pragma unroll
        for (int dd = 0; dd < NG; dd++) o[dd] = make_float4(0.f, 0.f, 0.f, 0.f);
#pragma unroll 4
        for (int s = 0; s < 32; s++) {
            float4 rv4 = *(const float4*)(rv + (size_t)s*CC);
#pragma unroll
            for (int dd = 0; dd < NG; dd++) {
                float aw = at[dd*(32*33) + t*33 + s];
                float4 v4 = *(const float4*)&kv[(dd*32 + s)*KST + f];
                o[dd].x = fmaf(aw, v4.x + rv4.x, o[dd].x);
                o[dd].y = fmaf(aw, v4.y + rv4.y, o[dd].y);
                o[dd].z = fmaf(aw, v4.z + rv4.z, o[dd].z);
                o[dd].w = fmaf(aw, v4.w + rv4.w, o[dd].w);
            }
        }
#pragma unroll
        for (int dd = 0; dd < NG; dd++)
            *(float4*)(ao + ((size_t)(bd0+dd)*TT + t)*CC + h*FF + f) = o[dd];
    }
}

// ---------------- launch ----------------
extern "C" void kernel_launch(void* const* d_in, const int* in_sizes, int n_in,
                              void* d_out, int out_size)
{
    const float* x      = (const float*)d_in[0];
    const float* temb   = (const float*)d_in[1];
    const int*   fi     = (const int*)  d_in[2];
    const int*   amask  = (const int*)  d_in[3];
    const float* norm_w = (const float*)d_in[4];
    const float* norm_b = (const float*)d_in[5];
    const float* qkv_w  = (const float*)d_in[6];
    const float* qkv_b  = (const float*)d_in[7];
    const float* proj_w = (const float*)d_in[8];
    const float* proj_b = (const float*)d_in[9];
    const float* dist_w[3]; const float* dist_b[3];
    const float* time_w[3]; const float* time_b[3];
    const float* out_w[3];  const float* out_b[3];
    for (int p = 0; p < 3; p++) {
        dist_w[p] = (const float*)d_in[10 + p*6 + 0];
        dist_b[p] = (const float*)d_in[10 + p*6 + 1];
        time_w[p] = (const float*)d_in[10 + p*6 + 2];
        time_b[p] = (const float*)d_in[10 + p*6 + 3];
        out_w[p]  = (const float*)d_in[10 + p*6 + 4];
        out_b[p]  = (const float*)d_in[10 + p*6 + 5];
    }

    float *xt, *qkvb, *tprj, *Rbuf, *ao;
    cudaGetSymbolAddress((void**)&xt,   g_xt);
    cudaGetSymbolAddress((void**)&qkvb, g_qkv);
    cudaGetSymbolAddress((void**)&tprj, g_tprj);
    cudaGetSymbolAddress((void**)&Rbuf, g_R);
    cudaGetSymbolAddress((void**)&ao,   g_ao);

    cudaFuncSetAttribute(gemm_tf32<0>, cudaFuncAttributeMaxDynamicSharedMemorySize, GEMM_SMEM);
    cudaFuncSetAttribute(gemm_tf32<1>, cudaFuncAttributeMaxDynamicSharedMemorySize, GEMM_SMEM);
    cudaFuncSetAttribute(gemm_tf32<2>, cudaFuncAttributeMaxDynamicSharedMemorySize, GEMM_SMEM);
    cudaFuncSetAttribute(attn_kernel, cudaFuncAttributeMaxDynamicSharedMemorySize, ATTN_SMEM);

    const int HUGE_ROWS = 1 << 30;

    // 1. temb projections: one launch, z = p, [64,1024] @ [512,1024]^T
    gemm_tf32<0><<<dim3(CC/128, 1, 3), 256, GEMM_SMEM>>>(
        temb, time_w[0], time_w[1], time_w[2], time_b[0], time_b[1], time_b[2],
        tprj, nullptr, nullptr, nullptr, nullptr, nullptr, nullptr, nullptr, nullptr,
        BB*TT, CC, TDIM, HUGE_ROWS, (size_t)BB*TT*CC);

    // 2. R = silu(tproj + dist feats) @ out_w[p]^T + out_b[p]  (rpe_h fused into A-load)
    gemm_tf32<2><<<dim3(CC/128, (3*BB*TT*TT)/128, 1), 256, GEMM_SMEM>>>(
        tprj, out_w[0], out_w[1], out_w[2], out_b[0], out_b[1], out_b[2],
        Rbuf, nullptr, fi,
        dist_w[0], dist_w[1], dist_w[2], dist_b[0], dist_b[1], dist_b[2],
        3*BB*TT*TT, CC, CC, BB*TT*TT, 0);

    // 3. GroupNorm + transpose -> xt [B,D,T,C]
    groupnorm_kernel<<<BB*DD, 512>>>(x, norm_w, norm_b, xt);

    // 4. QKV GEMM: [32768,512] @ [1536,512]^T   <-- profiled slot
    gemm_tf32<0><<<dim3(N_QKV/128, M_QKV/128, 1), 256, GEMM_SMEM>>>(
        xt, qkv_w, qkv_w, qkv_w, qkv_b, qkv_b, qkv_b,
        qkvb, nullptr, nullptr, nullptr, nullptr, nullptr, nullptr, nullptr, nullptr,
        M_QKV, N_QKV, CC, HUGE_ROWS, 0);

    // 5. attention (4 d's per block, 4 blocks/SM)
    attn_kernel<<<BB*(DD/NG)*HH, 256, ATTN_SMEM>>>(qkvb, Rbuf, amask, ao);

    // 6. proj + residual + transpose -> d_out [B,D,C,T]
    gemm_tf32<1><<<dim3(CC/128, M_QKV/128, 1), 256, GEMM_SMEM>>>(
        ao, proj_w, proj_w, proj_w, proj_b, proj_b, proj_b,
        (float*)d_out, xt, nullptr, nullptr, nullptr, nullptr, nullptr, nullptr, nullptr,
        M_QKV, CC, CC, HUGE_ROWS, 0);
}

// round 12
// speedup vs baseline: 1.3067x; 1.3067x over previous
#include <cuda_runtime.h>
#include <cstdint>

// Problem constants
#define BB 2
#define DD 512
#define CC 512
#define TT 32
#define TDIM 1024
#define HH 8
#define FF 64
#define SCALE 0.125f   // F^-0.5

#define M_QKV (BB*DD*TT)       // 32768
#define N_QKV (3*CC)           // 1536

// ---------------- scratch ----------------
__device__ float g_xt  [BB*DD*TT*CC];        // normalized, transposed x  [B,D,T,C]
__device__ float g_qkv [BB*DD*TT*3*CC];      // [B,D,T,3C]
__device__ float g_tprj[3*BB*TT*CC];         // [p,B,T,C]
__device__ float g_h   [3*BB*TT*TT*CC];      // silu(emb) [p,B,T,S,C]
__device__ float g_R   [3*BB*TT*TT*CC];      // rpe bias  [p,B,T,S,C]
__device__ float g_sb  [BB*HH*DD*TT*TT];     // score bias S2+S3, then probs P  [b,h,d,t,s]
__device__ float g_ao  [BB*DD*TT*CC];        // attention output pre-proj [B,D,T,C]

// ---------------- GroupNorm + transpose ----------------
__global__ __launch_bounds__(512) void groupnorm_kernel(
    const float* __restrict__ x, const float* __restrict__ w,
    const float* __restrict__ bv, float* __restrict__ xt)
{
    int bd = blockIdx.x;
    int c  = threadIdx.x;
    const float* xr = x + (size_t)bd * CC * TT + (size_t)c * TT;
    float v[TT];
    float s = 0.f, ss = 0.f;
#pragma unroll
    for (int i = 0; i < TT/4; i++) {
        float4 t4 = *(const float4*)(xr + i*4);
        v[i*4+0]=t4.x; v[i*4+1]=t4.y; v[i*4+2]=t4.z; v[i*4+3]=t4.w;
        s += t4.x+t4.y+t4.z+t4.w;
        ss += t4.x*t4.x + t4.y*t4.y + t4.z*t4.z + t4.w*t4.w;
    }
#pragma unroll
    for (int off = 8; off >= 1; off >>= 1) {
        s  += __shfl_xor_sync(0xffffffffu, s,  off);
        ss += __shfl_xor_sync(0xffffffffu, ss, off);
    }
    float mean = s * (1.f/512.f);
    float var  = ss * (1.f/512.f) - mean*mean;
    float rstd = rsqrtf(var + 1e-5f);
    float gw = w[c] * rstd;
    float gb = bv[c] - mean * gw;
    float* dst = xt + (size_t)bd * TT * CC + c;
#pragma unroll
    for (int t = 0; t < TT; t++) dst[(size_t)t*CC] = fmaf(v[t], gw, gb);
}

// ---------------- RPE: h = silu(tproj + feats@dw.T + db) ----------------
__global__ __launch_bounds__(256) void rpe_h_kernel(
    const float* __restrict__ tproj, const int* __restrict__ fi,
    const float* __restrict__ qdw, const float* __restrict__ qdb,
    const float* __restrict__ kdw, const float* __restrict__ kdb,
    const float* __restrict__ vdw, const float* __restrict__ vdb,
    float* __restrict__ h)
{
    int idx = blockIdx.x * 256 + threadIdx.x;      // [p,b,t,s,c]
    int c = idx & 511;
    int s = (idx >> 9) & 31;
    int t = (idx >> 14) & 31;
    int b = (idx >> 19) & 1;
    int p = idx >> 20;
    int d = fi[b*TT + t] - fi[b*TT + s];
    float df = (float)d;
    float f0 = log1pf(fmaxf(df, 0.f));
    float f1 = log1pf(fmaxf(-df, 0.f));
    float f2 = (d == 0) ? 1.f : 0.f;
    const float* dw = (p == 0) ? qdw : ((p == 1) ? kdw : vdw);
    const float* db = (p == 0) ? qdb : ((p == 1) ? kdb : vdb);
    float e = tproj[(size_t)((p*BB + b)*TT + t) * CC + c]
            + dw[c*3+0]*f0 + dw[c*3+1]*f1 + dw[c*3+2]*f2 + db[c];
    float sig = 1.f / (1.f + __expf(-e));
    h[idx] = e * sig;
}

// ---------------- tf32 tensor-core NT GEMM, 3-stage cp.async ----------------
// MODE 0: plain store. MODE 1: +resid, transposed store.
#define GS 36
#define GSTAGE (128*GS)              // floats per operand per stage
#define GEMM_SMEM (3*2*GSTAGE*4)     // 3 stages x (A+B) = 110592 bytes

__device__ __forceinline__ void cp16(uint32_t dst, const float* src, int sz) {
    asm volatile("cp.async.cg.shared.global [%0], [%1], 16, %2;\n"
                 :: "r"(dst), "l"(src), "r"(sz));
}

template<int MODE>
__global__ __launch_bounds__(256, 2) void gemm_tf32(
    const float* __restrict__ A,
    const float* __restrict__ W0, const float* __restrict__ W1, const float* __restrict__ W2,
    const float* __restrict__ B0, const float* __restrict__ B1, const float* __restrict__ B2,
    float* __restrict__ out, const float* __restrict__ resid,
    int M, int N, int K, int rows_per_w, size_t out_z_stride)
{
    extern __shared__ float sh[];

    int bm = blockIdx.y * 128, bn = blockIdx.x * 128;
    int p = (gridDim.z > 1) ? blockIdx.z : (bm / rows_per_w);
    const float* W    = (p == 0) ? W0 : ((p == 1) ? W1 : W2);
    const float* bias = (p == 0) ? B0 : ((p == 1) ? B1 : B2);
    float* outp = out + (size_t)blockIdx.z * out_z_stride;

    int tid  = threadIdx.x;
    int warp = tid >> 5, lane = tid & 31;
    int gq = lane >> 2, tg = lane & 3;
    int wm = (warp >> 1) * 32;
    int wn = (warp & 1) * 64;

    int lrow = tid >> 1;           // 0..127
    int lk   = (tid & 1) * 16;     // 0 or 16

    const float* Ap = A + (size_t)(bm + lrow) * K + lk;
    const float* Wp = W + (size_t)(bn + lrow) * K + lk;
    int a_sz = ((bm + lrow) < M) ? 16 : 0;   // zero-fill OOB rows (tproj M=64)
    uint32_t shb = (uint32_t)__cvta_generic_to_shared(sh);
    uint32_t sAoff = shb + (uint32_t)(lrow*GS + lk)*4;

    float acc[2][8][4] = {};
    int nt = K >> 5;

    auto fill = [&](int st, int k0) {
        uint32_t da = sAoff + (uint32_t)(st*2*GSTAGE)*4;
        uint32_t db = da + (uint32_t)GSTAGE*4;
#pragma unroll
        for (int v = 0; v < 4; v++) {
            cp16(da + v*16, Ap + k0 + v*4, a_sz);
            cp16(db + v*16, Wp + k0 + v*4, 16);
        }
    };

    // prologue: stages 0 and 1 (nt >= 16 always for our shapes)
    fill(0, 0);  asm volatile("cp.async.commit_group;\n");
    fill(1, 32); asm volatile("cp.async.commit_group;\n");

    for (int it = 0; it < nt; it++) {
        int cur = it % 3;
        if (it + 2 < nt) {
            fill((it+2) % 3, (it+2)*32);
            asm volatile("cp.async.commit_group;\n");
            asm volatile("cp.async.wait_group 2;\n");
        } else {
            asm volatile("cp.async.wait_group 0;\n");
        }
        __syncthreads();

        const float* Ac = sh + cur*2*GSTAGE;
        const float* Bc = Ac + GSTAGE;
#pragma unroll
        for (int ks = 0; ks < 4; ks++) {
            int kk = ks * 8;
            unsigned a[2][4];
#pragma unroll
            for (int i = 0; i < 2; i++) {
                int m = wm + i*16 + gq;
                a[i][0] = __float_as_uint(Ac[(m    )*GS + kk + tg    ]);
                a[i][1] = __float_as_uint(Ac[(m + 8)*GS + kk + tg    ]);
                a[i][2] = __float_as_uint(Ac[(m    )*GS + kk + tg + 4]);
                a[i][3] = __float_as_uint(Ac[(m + 8)*GS + kk + tg + 4]);
            }
            unsigned bf[8][2];
#pragma unroll
            for (int j = 0; j < 8; j++) {
                int n = wn + j*8 + gq;
                bf[j][0] = __float_as_uint(Bc[n*GS + kk + tg    ]);
                bf[j][1] = __float_as_uint(Bc[n*GS + kk + tg + 4]);
            }
#pragma unroll
            for (int i = 0; i < 2; i++)
#pragma unroll
                for (int j = 0; j < 8; j++) {
                    asm volatile(
                        "mma.sync.aligned.m16n8k8.row.col.f32.tf32.tf32.f32 "
                        "{%0,%1,%2,%3}, {%4,%5,%6,%7}, {%8,%9}, {%0,%1,%2,%3};\n"
                        : "+f"(acc[i][j][0]), "+f"(acc[i][j][1]),
                          "+f"(acc[i][j][2]), "+f"(acc[i][j][3])
                        : "r"(a[i][0]), "r"(a[i][1]), "r"(a[i][2]), "r"(a[i][3]),
                          "r"(bf[j][0]), "r"(bf[j][1]));
                }
        }
        __syncthreads();
    }

    // epilogue
#pragma unroll
    for (int i = 0; i < 2; i++) {
        int m0 = bm + wm + i*16 + gq;
        int m1 = m0 + 8;
#pragma unroll
        for (int j = 0; j < 8; j++) {
            int n0 = bn + wn + j*8 + tg*2;
            float bn0 = bias[n0], bn1 = bias[n0+1];
            float v00 = acc[i][j][0] + bn0, v01 = acc[i][j][1] + bn1;
            float v10 = acc[i][j][2] + bn0, v11 = acc[i][j][3] + bn1;
            if (MODE == 1) {
                v00 += resid[(size_t)m0*N + n0];
                v01 += resid[(size_t)m0*N + n0+1];
                v10 += resid[(size_t)m1*N + n0];
                v11 += resid[(size_t)m1*N + n0+1];
                size_t b0 = (size_t)(m0 >> 5) * (512*32);
                size_t b1 = (size_t)(m1 >> 5) * (512*32);
                outp[b0 + (size_t)(n0  )*32 + (m0 & 31)] = v00;
                outp[b0 + (size_t)(n0+1)*32 + (m0 & 31)] = v01;
                outp[b1 + (size_t)(n0  )*32 + (m1 & 31)] = v10;
                outp[b1 + (size_t)(n0+1)*32 + (m1 & 31)] = v11;
            } else {
                if (m0 < M) { outp[(size_t)m0*N + n0] = v00; outp[(size_t)m0*N + n0+1] = v01; }
                if (m1 < M) { outp[(size_t)m1*N + n0] = v10; outp[(size_t)m1*N + n0+1] = v11; }
            }
        }
    }
}

// ---------------- batched small GEMM (tf32) for RPE einsums ----------------
// MODE 0 (S2):  per z=(b,h,t): q[d,f] @ Rk[s,f]^T  -> sb[b,h,d,t,s]   (store)
// MODE 1 (S3):  per z=(b,h,s): k[d,f] @ Rq[t,f]^T  -> sb[b,h,d,t,s]   (+=)
// MODE 2 (out2):per z=(b,h,t): P[d,s] @ Rv[s,f]    -> ao[b,d,t,h*64+f](+=)
//   NOTE MODE 2: B tile Rv is [k=s][n=f] in memory (opposite of modes 0/1
//   where it is [n][k]); stored as loaded, B-fragment indexing transposed.
template<int MODE>
__global__ __launch_bounds__(256) void bgemm(
    const float* __restrict__ qkv, const float* __restrict__ R,
    float* __restrict__ sb, float* __restrict__ ao)
{
    constexpr int KK = (MODE == 2) ? 32 : 64;
    constexpr int NN = (MODE == 2) ? 64 : 32;
    constexpr int KPA = KK + 4;
    constexpr int NJ = NN / 8;
    __shared__ float As[128*KPA];
    __shared__ float Bs[32*68];    // 32 rows x 64 floats (+4 pad), both layouts

    int z = blockIdx.y, mt = blockIdx.x;
    int b = z >> 8, h = (z >> 5) & 7, x = z & 31;

    const float* Abase; const float* Bbase; float* obase;
    size_t Arst, orst, ocst;
    if (MODE == 0) {
        Abase = qkv + ((size_t)(b*DD)*TT + x)*N_QKV + h*FF;
        Arst  = (size_t)TT*N_QKV;
        Bbase = R + ((size_t)((1*BB + b)*TT*TT) + x*TT)*CC + h*FF;   // Rk[b,t=x,s]
        obase = sb + ((size_t)(b*HH + h)*DD)*(TT*TT) + x*TT;
        orst = TT*TT; ocst = 1;
    } else if (MODE == 1) {
        Abase = qkv + ((size_t)(b*DD)*TT + x)*N_QKV + CC + h*FF;
        Arst  = (size_t)TT*N_QKV;
        Bbase = R + ((size_t)((0*BB + b)*TT*TT) + x*TT)*CC + h*FF;   // Rq[b,s=x,t]
        obase = sb + ((size_t)(b*HH + h)*DD)*(TT*TT) + x;
        orst = TT*TT; ocst = TT;
    } else {
        Abase = sb + ((size_t)(b*HH + h)*DD)*(TT*TT) + x*TT;          // P[d,s]
        Arst  = TT*TT;
        Bbase = R + ((size_t)((2*BB + b)*TT*TT) + x*TT)*CC + h*FF;   // Rv[b,t=x,s]
        obase = ao + ((size_t)(b*DD)*TT + x)*CC + h*FF;
        orst = (size_t)TT*CC; ocst = 1;
    }
    Abase += (size_t)mt * 128 * Arst;
    obase += (size_t)mt * 128 * orst;

    int tid = threadIdx.x;
    constexpr int RF4A = KK/4;
#pragma unroll
    for (int i = 0; i < 128*KK/1024; i++) {
        int e = i*256 + tid;
        int r = e / RF4A, c4 = e % RF4A;
        *(float4*)&As[r*KPA + c4*4] = *(const float4*)(Abase + (size_t)r*Arst + c4*4);
    }
    // B: 32 rows x 64 floats from Bbase + r*CC (all modes)
#pragma unroll
    for (int i = 0; i < 2; i++) {
        int e = i*256 + tid;
        int r = e >> 4, c4 = e & 15;
        *(float4*)&Bs[r*68 + c4*4] = *(const float4*)(Bbase + (size_t)r*CC + c4*4);
    }
    __syncthreads();

    int warp = tid >> 5, lane = tid & 31;
    int gq = lane >> 2, tg = lane & 3;
    int wm = warp * 16;

    float acc[NJ][4] = {};
#pragma unroll
    for (int kk = 0; kk < KK; kk += 8) {
        unsigned a0 = __float_as_uint(As[(wm + gq    )*KPA + kk + tg    ]);
        unsigned a1 = __float_as_uint(As[(wm + 8 + gq)*KPA + kk + tg    ]);
        unsigned a2 = __float_as_uint(As[(wm + gq    )*KPA + kk + tg + 4]);
        unsigned a3 = __float_as_uint(As[(wm + 8 + gq)*KPA + kk + tg + 4]);
#pragma unroll
        for (int j = 0; j < NJ; j++) {
            unsigned b0, b1;
            if (MODE == 2) {   // Bs[k=s][n=f]
                b0 = __float_as_uint(Bs[(kk + tg    )*68 + j*8 + gq]);
                b1 = __float_as_uint(Bs[(kk + tg + 4)*68 + j*8 + gq]);
            } else {           // Bs[n][k]
                b0 = __float_as_uint(Bs[(j*8 + gq)*68 + kk + tg    ]);
                b1 = __float_as_uint(Bs[(j*8 + gq)*68 + kk + tg + 4]);
            }
            asm volatile(
                "mma.sync.aligned.m16n8k8.row.col.f32.tf32.tf32.f32 "
                "{%0,%1,%2,%3}, {%4,%5,%6,%7}, {%8,%9}, {%0,%1,%2,%3};\n"
                : "+f"(acc[j][0]), "+f"(acc[j][1]), "+f"(acc[j][2]), "+f"(acc[j][3])
                : "r"(a0), "r"(a1), "r"(a2), "r"(a3), "r"(b0), "r"(b1));
        }
    }

#pragma unroll
    for (int j = 0; j < NJ; j++) {
        int r0 = wm + gq, r1 = r0 + 8;
        int c0 = j*8 + tg*2;
        float* p00 = obase + (size_t)r0*orst + (size_t)c0*ocst;
        float* p01 = obase + (size_t)r0*orst + (size_t)(c0+1)*ocst;
        float* p10 = obase + (size_t)r1*orst + (size_t)c0*ocst;
        float* p11 = obase + (size_t)r1*orst + (size_t)(c0+1)*ocst;
        if (MODE == 0) {
            *p00 = acc[j][0]; *p01 = acc[j][1]; *p10 = acc[j][2]; *p11 = acc[j][3];
        } else {
            *p00 += acc[j][0]; *p01 += acc[j][1]; *p10 += acc[j][2]; *p11 += acc[j][3];
        }
    }
}

// ---------------- attention core: block per (b, d-group of 8, h) ----------------
// scores = SCALE*(q.k + sb), softmax, out1 = attn@v, probs -> sb (in place)
#define NG 8
#define KST 68
#define ATTN_SMEM ((NG*32*KST + NG*32*33)*4 + 128)

__global__ __launch_bounds__(256, 2) void attn_kernel(
    const float* __restrict__ qkv, float* __restrict__ sb,
    const int* __restrict__ mask, float* __restrict__ ao)
{
    extern __shared__ float sm[];
    float* kv = sm;                    // [NG*32][KST], K then V
    float* at = kv + NG*32*KST;        // [NG][32*33]
    int*  msk = (int*)(at + NG*32*33);

    int tid = threadIdx.x;
    int h = blockIdx.x & 7;
    int g = blockIdx.x >> 3;
    int b = g >> 6;                    // D/NG = 64
    int d0 = (g & 63) * NG;
    int bd0 = b*DD + d0;

    // load K tiles
    for (int e = tid; e < NG*32*16; e += 256) {
        int dd = e >> 9;
        int t  = (e >> 4) & 31;
        int f  = (e & 15) * 4;
        const float* rowp = qkv + ((size_t)(bd0+dd)*TT + t)*N_QKV + h*FF + f;
        *(float4*)&kv[(dd*32 + t)*KST + f] = *(const float4*)(rowp + CC);
    }
    if (tid < 32) msk[tid] = mask[b*TT + tid];
    __syncthreads();

    float* sbblk = sb + ((size_t)(b*HH + h)*DD + d0)*(TT*TT);

    // scores
#pragma unroll 1
    for (int pi = 0; pi < 4; pi++) {
        int pid = pi*256 + tid;
        int t = pid >> 5, s = pid & 31;
        const float* qb = qkv + ((size_t)bd0*TT + t)*N_QKV + h*FF;
        float acc[NG] = {};
#pragma unroll
        for (int f = 0; f < FF; f += 4) {
#pragma unroll
            for (int dd = 0; dd < NG; dd++) {
                float4 q4 = *(const float4*)(qb + (size_t)dd*TT*N_QKV + f);
                float4 k4 = *(const float4*)&kv[(dd*32 + s)*KST + f];
                acc[dd] = fmaf(q4.x, k4.x, acc[dd]);
                acc[dd] = fmaf(q4.y, k4.y, acc[dd]);
                acc[dd] = fmaf(q4.z, k4.z, acc[dd]);
                acc[dd] = fmaf(q4.w, k4.w, acc[dd]);
            }
        }
        bool bad = (msk[t] != msk[s]);
#pragma unroll
        for (int dd = 0; dd < NG; dd++) {
            float bias = sbblk[(size_t)dd*(TT*TT) + t*32 + s];
            at[dd*(32*33) + t*33 + s] = bad ? -1e30f : SCALE*(acc[dd] + bias);
        }
    }
    __syncthreads();

    // softmax: 256 threads = NG*32 rows
    {
        int dd = tid >> 5, t = tid & 31;
        float* row = &at[dd*(32*33) + t*33];
        float mx = -1e30f;
#pragma unroll
        for (int s = 0; s < 32; s++) mx = fmaxf(mx, row[s]);
        float sum = 0.f;
#pragma unroll
        for (int s = 0; s < 32; s++) { float e = __expf(row[s] - mx); row[s] = e; sum += e; }
        float inv = 1.f / sum;
#pragma unroll
        for (int s = 0; s < 32; s++) row[s] *= inv;
    }
    __syncthreads();

    // write probs back to sb (in place), and load V into kv
    for (int e = tid; e < NG*32*8; e += 256) {
        int dd = e >> 8;
        int t  = (e >> 3) & 31;
        int s4 = (e & 7) * 4;
        float* a0 = &at[dd*(32*33) + t*33 + s4];
        float4 p4 = make_float4(a0[0], a0[1], a0[2], a0[3]);
        *(float4*)&sbblk[(size_t)dd*(TT*TT) + t*32 + s4] = p4;
    }
    for (int e = tid; e < NG*32*16; e += 256) {
        int dd = e >> 9;
        int t  = (e >> 4) & 31;
        int f  = (e & 15) * 4;
        const float* rowp = qkv + ((size_t)(bd0+dd)*TT + t)*N_QKV + h*FF + f;
        *(float4*)&kv[(dd*32 + t)*KST + f] = *(const float4*)(rowp + 2*CC);
    }
    __syncthreads();

    // out1 = attn @ v
#pragma unroll 1
    for (int ui = 0; ui < 2; ui++) {
        int u = ui*256 + tid;
        int t = u >> 4, f = (u & 15) * 4;
        float4 o[NG];
#pragma unroll
        for (int dd = 0; dd < NG; dd++) o[dd] = make_float4(0.f, 0.f, 0.f, 0.f);
#pragma unroll 4
        for (int s = 0; s < 32; s++) {
#pragma unroll
            for (int dd = 0; dd < NG; dd++) {
                float aw = at[dd*(32*33) + t*33 + s];
                float4 v4 = *(const float4*)&kv[(dd*32 + s)*KST + f];
                o[dd].x = fmaf(aw, v4.x, o[dd].x);
                o[dd].y = fmaf(aw, v4.y, o[dd].y);
                o[dd].z = fmaf(aw, v4.z, o[dd].z);
                o[dd].w = fmaf(aw, v4.w, o[dd].w);
            }
        }
#pragma unroll
        for (int dd = 0; dd < NG; dd++)
            *(float4*)(ao + ((size_t)(bd0+dd)*TT + t)*CC + h*FF + f) = o[dd];
    }
}

// ---------------- launch ----------------
extern "C" void kernel_launch(void* const* d_in, const int* in_sizes, int n_in,
                              void* d_out, int out_size)
{
    const float* x      = (const float*)d_in[0];
    const float* temb   = (const float*)d_in[1];
    const int*   fi     = (const int*)  d_in[2];
    const int*   amask  = (const int*)  d_in[3];
    const float* norm_w = (const float*)d_in[4];
    const float* norm_b = (const float*)d_in[5];
    const float* qkv_w  = (const float*)d_in[6];
    const float* qkv_b  = (const float*)d_in[7];
    const float* proj_w = (const float*)d_in[8];
    const float* proj_b = (const float*)d_in[9];
    const float* dist_w[3]; const float* dist_b[3];
    const float* time_w[3]; const float* time_b[3];
    const float* out_w[3];  const float* out_b[3];
    for (int p = 0; p < 3; p++) {
        dist_w[p] = (const float*)d_in[10 + p*6 + 0];
        dist_b[p] = (const float*)d_in[10 + p*6 + 1];
        time_w[p] = (const float*)d_in[10 + p*6 + 2];
        time_b[p] = (const float*)d_in[10 + p*6 + 3];
        out_w[p]  = (const float*)d_in[10 + p*6 + 4];
        out_b[p]  = (const float*)d_in[10 + p*6 + 5];
    }

    float *xt, *qkvb, *tprj, *hbuf, *Rbuf, *sbb, *ao;
    cudaGetSymbolAddress((void**)&xt,   g_xt);
    cudaGetSymbolAddress((void**)&qkvb, g_qkv);
    cudaGetSymbolAddress((void**)&tprj, g_tprj);
    cudaGetSymbolAddress((void**)&hbuf, g_h);
    cudaGetSymbolAddress((void**)&Rbuf, g_R);
    cudaGetSymbolAddress((void**)&sbb,  g_sb);
    cudaGetSymbolAddress((void**)&ao,   g_ao);

    cudaFuncSetAttribute(gemm_tf32<0>, cudaFuncAttributeMaxDynamicSharedMemorySize, GEMM_SMEM);
    cudaFuncSetAttribute(gemm_tf32<1>, cudaFuncAttributeMaxDynamicSharedMemorySize, GEMM_SMEM);
    cudaFuncSetAttribute(attn_kernel, cudaFuncAttributeMaxDynamicSharedMemorySize, ATTN_SMEM);

    const int HUGE_ROWS = 1 << 30;

    // 1. temb projections: one launch, z = p, [64,1024] @ [512,1024]^T
    gemm_tf32<0><<<dim3(CC/128, 1, 3), 256, GEMM_SMEM>>>(
        temb, time_w[0], time_w[1], time_w[2], time_b[0], time_b[1], time_b[2],
        tprj, nullptr, BB*TT, CC, TDIM, HUGE_ROWS, (size_t)BB*TT*CC);

    // 2. h = silu(emb)
    rpe_h_kernel<<<(3*BB*TT*TT*CC)/256, 256>>>(tprj, fi,
        dist_w[0], dist_b[0], dist_w[1], dist_b[1], dist_w[2], dist_b[2], hbuf);

    // 3. GroupNorm + transpose -> xt [B,D,T,C]
    groupnorm_kernel<<<BB*DD, 512>>>(x, norm_w, norm_b, xt);

    // 4. QKV GEMM (profiled slot): [32768,512] @ [1536,512]^T, 3-stage pipeline
    gemm_tf32<0><<<dim3(N_QKV/128, M_QKV/128, 1), 256, GEMM_SMEM>>>(
        xt, qkv_w, qkv_w, qkv_w, qkv_b, qkv_b, qkv_b,
        qkvb, nullptr, M_QKV, N_QKV, CC, HUGE_ROWS, 0);

    // 5. R = h @ out_w[p]^T + out_b[p], weight stripe every 2048 rows
    gemm_tf32<0><<<dim3(CC/128, (3*BB*TT*TT)/128, 1), 256, GEMM_SMEM>>>(
        hbuf, out_w[0], out_w[1], out_w[2], out_b[0], out_b[1], out_b[2],
        Rbuf, nullptr, 3*BB*TT*TT, CC, CC, BB*TT*TT, 0);

    // 6. S2 = q @ Rk^T -> sb
    bgemm<0><<<dim3(4, BB*HH*TT), 256>>>(qkvb, Rbuf, sbb, ao);
    // 7. S3 = k @ Rq^T -> sb +=
    bgemm<1><<<dim3(4, BB*HH*TT), 256>>>(qkvb, Rbuf, sbb, ao);

    // 8. attention core: softmax + attn@v; probs into sb
    attn_kernel<<<BB*(DD/NG)*HH, 256, ATTN_SMEM>>>(qkvb, sbb, amask, ao);

    // 9. out2 = P @ Rv -> ao +=
    bgemm<2><<<dim3(4, BB*HH*TT), 256>>>(qkvb, Rbuf, sbb, ao);

    // 10. proj + residual + transpose -> d_out [B,D,C,T]
    gemm_tf32<1><<<dim3(CC/128, M_QKV/128, 1), 256, GEMM_SMEM>>>(
        ao, proj_w, proj_w, proj_w, proj_b, proj_b, proj_b,
        (float*)d_out, xt, M_QKV, CC, CC, HUGE_ROWS, 0);
}